// round 5
// baseline (speedup 1.0000x reference)
#include <cuda_runtime.h>
#include <math.h>

#define NTHR   512
#define NW     (NTHR / 32)        // 16 warps
#define HID    512
#define TENC   16384
#define NVOCAB 31
#define MAXLEN 100
#define EOSI   29
#define PADV   30.0f
#define NBUF   3
#define MAXBLK 256
#define PCACHE 34                 // enc rows pinned in smem per block

// ---------------- device scratch ----------------
__device__ __align__(16) float g_sumv[NBUF][HID];     // attention summary accumulators
__device__ float g_tot[NBUF];                         // softmax denominators
__device__ __align__(16) float g_gh[2][3][HID];       // w_hh@h + b_hh (r,z,n), double buffered
__device__ __align__(16) float g_gx[NVOCAB][3 * HID]; // w_ih@embed[v] + b_ih
__device__ float g_lh[NVOCAB];                        // w_out[:,512:]@h + b_out (per step)
__device__ volatile int g_arrive[MAXBLK];

__device__ __forceinline__ float warp_allsum(float v) {
    #pragma unroll
    for (int o = 16; o; o >>= 1) v += __shfl_xor_sync(0xffffffffu, v, o);
    return v;
}

extern __shared__ float s_dyn[];   // [PCACHE*1024] enc rows | [31*512] w_out summary half

__global__ void __launch_bounds__(NTHR, 1)
decoder_kernel(const float* __restrict__ enc,     // [TENC, 1024] keys|values
               const float* __restrict__ embed,   // [31, 512]
               const float* __restrict__ w_ih,    // [1536, 512]
               const float* __restrict__ w_hh,    // [1536, 512]
               const float* __restrict__ b_ih,    // [1536]
               const float* __restrict__ b_hh,    // [1536]
               const float* __restrict__ w_out,   // [31, 1024]
               const float* __restrict__ b_out,   // [31]
               float* __restrict__ out)
{
    const int tid  = threadIdx.x;
    const int blk  = blockIdx.x;
    const int nblk = gridDim.x;
    const int wid  = tid >> 5;
    const int lane = tid & 31;
    const int base = lane * 4;

    float* s_enc   = s_dyn;                   // PCACHE rows of enc
    float* s_woutS = s_dyn + PCACHE * 1024;   // [31][512] summary-half of w_out

    __shared__ __align__(16) float s_hh[HID];          // h (per-block copy)
    __shared__ __align__(16) float s_sum[HID];         // normalized summary
    __shared__ __align__(16) float s_warp[8][HID];     // merge buffers
    __shared__ float s_exp[128];
    __shared__ float s_lh[NVOCAB];
    __shared__ float s_logit[NVOCAB];
    __shared__ float s_red[NW];
    __shared__ int   s_best;

    float* out_logits = out;                        // [100, 31]
    float* out_len    = out + MAXLEN * NVOCAB;      // [1]
    float* out_attn   = out + MAXLEN * NVOCAB + 1;  // [100, 16384]

    int ep = g_arrive[blk];   // monotonic across launches; equal in all blocks at start

    auto grid_barrier = [&]() {
        ep++;
        __syncthreads();
        __threadfence();
        if (tid == 0) g_arrive[blk] = ep;
        for (int i = tid; i < nblk; i += NTHR)
            while (g_arrive[i] < ep) { }
        __threadfence();
        __syncthreads();
    };

    // ---------------- per-launch init ----------------
    s_hh[tid] = 0.0f;                     // h0 = 0   (NTHR == HID)
    if (tid == 0) s_best = EOSI;          // y0 = embed[EOS]

    // row partition: blocks 0..31 (gh duty) get `light`, rest `heavy` = light+13
    const int heavy = (TENC + 13 * 32 + nblk - 1) / nblk;
    const int light = heavy - 13;
    int t0 = (blk < 32) ? blk * light : 32 * light + (blk - 32) * heavy;
    int t1 = t0 + ((blk < 32) ? light : heavy);
    if (t0 > TENC) t0 = TENC;
    if (t1 > TENC) t1 = TENC;
    const int ts = t0 + PCACHE;          // stream start (cnt per block always > PCACHE)

    // pin first PCACHE rows of our range into smem (once per launch)
    for (int i = tid; i < PCACHE * 1024; i += NTHR)
        s_enc[i] = __ldcg(enc + (size_t)t0 * 1024 + i);
    // w_out summary half -> smem
    for (int i = tid; i < NVOCAB * HID; i += NTHR)
        s_woutS[i] = w_out[(size_t)(i >> 9) * 1024 + (i & 511)];

    if (blk == 0) {
        #pragma unroll
        for (int b = 0; b < NBUF; ++b) g_sumv[b][tid] = 0.0f;
        g_gh[0][0][tid] = b_hh[tid];
        g_gh[0][1][tid] = b_hh[tid + HID];
        g_gh[0][2][tid] = b_hh[tid + 2 * HID];
        if (tid == 0) { g_tot[0] = 0.0f; g_tot[1] = 0.0f; g_tot[2] = 0.0f; }
    }
    // gx table: gx[v][u] = w_ih[u] . embed[v] + b_ih[u]
    {
        const int gw = blk * NW + wid;
        for (int r = gw; r < NVOCAB * 3 * HID; r += nblk * NW) {
            const int v = r / (3 * HID);
            const int u = r - v * (3 * HID);
            const float* wrow = w_ih + (size_t)u * HID;
            const float* erow = embed + (size_t)v * HID;
            float a = 0.0f;
            #pragma unroll
            for (int m = 0; m < 4; ++m) {
                int c = base + m * 128;
                float4 w4 = *(const float4*)(wrow + c);
                float4 e4 = *(const float4*)(erow + c);
                a = fmaf(w4.x, e4.x, fmaf(w4.y, e4.y, fmaf(w4.z, e4.z, fmaf(w4.w, e4.w, a))));
            }
            a = warp_allsum(a);
            if (lane == 0) g_gx[v][u] = a + b_ih[u];
        }
    }
    int eos_step = MAXLEN;

    grid_barrier();

    const float scale = 0.04419417382415922f;   // 1/sqrt(512)

    for (int k = 0; k <= MAXLEN; ++k) {
        // ============ Phase A: epilogue of step k-1 (redundant per block) ============
        if (k > 0) {
            const int p = (k - 1) % NBUF;
            const float inv_total = 1.0f / __ldcg(&g_tot[p]);

            for (int t = t0 + tid; t < t1; t += NTHR)
                out_attn[(size_t)(k - 1) * TENC + t] = s_exp[t - t0] * inv_total;

            s_sum[tid] = __ldcg(&g_sumv[p][tid]) * inv_total;
            if (tid < NVOCAB) s_lh[tid] = __ldcg(&g_lh[tid]);

            if (blk == 0) {                       // zero buffer (k+1)%3
                const int zb = (k + 1) % NBUF;
                g_sumv[zb][tid] = 0.0f;
                if (tid == 0) g_tot[zb] = 0.0f;
            }
            __syncthreads();

            // logits: summary half from smem w_out; h half from g_lh
            for (int v = wid; v < NVOCAB; v += NW) {
                const float* wrow = s_woutS + v * HID;
                float dot = 0.0f;
                #pragma unroll
                for (int m = 0; m < 4; ++m) {
                    int c = base + m * 128;
                    float4 w4 = *(const float4*)(wrow + c);
                    float4 x4 = *(const float4*)(s_sum + c);
                    dot = fmaf(w4.x, x4.x, fmaf(w4.y, x4.y, fmaf(w4.z, x4.z, fmaf(w4.w, x4.w, dot))));
                }
                dot = warp_allsum(dot);
                if (lane == 0) {
                    dot += s_lh[v];
                    s_logit[v] = dot;
                    if (blk == 0) out_logits[(k - 1) * NVOCAB + v] = dot;
                }
            }
            __syncthreads();
            if (tid == 0) {
                int best = 0; float bv = s_logit[0];
                #pragma unroll
                for (int v = 1; v < NVOCAB; ++v)
                    if (s_logit[v] > bv) { bv = s_logit[v]; best = v; }
                s_best = best;
                if (blk == 0 && best == EOSI && eos_step == MAXLEN) eos_step = k - 1;
            }
            __syncthreads();
        }

        if (k == MAXLEN) break;

        // GRU pointwise: h^{(k)} = GRU(gx[best], gh, h^{(k-1)})
        {
            const float* gx = g_gx[s_best];
            const int pg = k & 1;
            float r = 1.0f / (1.0f + __expf(-(gx[tid]           + __ldcg(&g_gh[pg][0][tid]))));
            float z = 1.0f / (1.0f + __expf(-(gx[tid + HID]     + __ldcg(&g_gh[pg][1][tid]))));
            float n = tanhf(gx[tid + 2 * HID] + r * __ldcg(&g_gh[pg][2][tid]));
            s_hh[tid] = (1.0f - z) * n + z * s_hh[tid];
        }
        __syncthreads();

        // ============ Phase B: attention sweep ============
        float4 h0 = *(const float4*)(s_hh + base);
        float4 h1 = *(const float4*)(s_hh + base + 128);
        float4 h2 = *(const float4*)(s_hh + base + 256);
        float4 h3 = *(const float4*)(s_hh + base + 384);

        // lh for next epilogue: block 32+v computes w_out[v,512:].h + b_out[v]
        if (wid == 0 && blk >= 32 && blk < 32 + NVOCAB) {
            const int v = blk - 32;
            const float* wrow = w_out + (size_t)v * 1024 + HID;
            float dot = 0.0f;
            float4 w4;
            w4 = *(const float4*)(wrow + base);
            dot = fmaf(w4.x, h0.x, fmaf(w4.y, h0.y, fmaf(w4.z, h0.z, fmaf(w4.w, h0.w, dot))));
            w4 = *(const float4*)(wrow + base + 128);
            dot = fmaf(w4.x, h1.x, fmaf(w4.y, h1.y, fmaf(w4.z, h1.z, fmaf(w4.w, h1.w, dot))));
            w4 = *(const float4*)(wrow + base + 256);
            dot = fmaf(w4.x, h2.x, fmaf(w4.y, h2.y, fmaf(w4.z, h2.z, fmaf(w4.w, h2.w, dot))));
            w4 = *(const float4*)(wrow + base + 384);
            dot = fmaf(w4.x, h3.x, fmaf(w4.y, h3.y, fmaf(w4.z, h3.z, fmaf(w4.w, h3.w, dot))));
            dot = warp_allsum(dot);
            if (lane == 0) g_lh[v] = dot + b_out[v];
        }

        float4 acc0 = {0,0,0,0}, acc1 = {0,0,0,0}, acc2 = {0,0,0,0}, acc3 = {0,0,0,0};
        float esum = 0.0f;

        // ---- streamed rows (L2, __ldcg), 2 rows per warp-iter ----
        for (int ta = ts + wid; ta < t1; ta += NW * 2) {
            const int tb   = ta + NW;
            const int bok  = (tb < t1);
            const int trb  = bok ? tb : ta;
            const float* ra = enc + (size_t)ta  * (2 * HID);
            const float* rb = enc + (size_t)trb * (2 * HID);
            float4 ka0 = __ldcg((const float4*)(ra + base));
            float4 ka1 = __ldcg((const float4*)(ra + base + 128));
            float4 ka2 = __ldcg((const float4*)(ra + base + 256));
            float4 ka3 = __ldcg((const float4*)(ra + base + 384));
            float4 va0 = __ldcg((const float4*)(ra + HID + base));
            float4 va1 = __ldcg((const float4*)(ra + HID + base + 128));
            float4 va2 = __ldcg((const float4*)(ra + HID + base + 256));
            float4 va3 = __ldcg((const float4*)(ra + HID + base + 384));
            float4 kb0 = __ldcg((const float4*)(rb + base));
            float4 kb1 = __ldcg((const float4*)(rb + base + 128));
            float4 kb2 = __ldcg((const float4*)(rb + base + 256));
            float4 kb3 = __ldcg((const float4*)(rb + base + 384));
            float4 vb0 = __ldcg((const float4*)(rb + HID + base));
            float4 vb1 = __ldcg((const float4*)(rb + HID + base + 128));
            float4 vb2 = __ldcg((const float4*)(rb + HID + base + 256));
            float4 vb3 = __ldcg((const float4*)(rb + HID + base + 384));

            float da = 0.0f, db = 0.0f;
            da = fmaf(ka0.x, h0.x, fmaf(ka0.y, h0.y, fmaf(ka0.z, h0.z, fmaf(ka0.w, h0.w, da))));
            da = fmaf(ka1.x, h1.x, fmaf(ka1.y, h1.y, fmaf(ka1.z, h1.z, fmaf(ka1.w, h1.w, da))));
            da = fmaf(ka2.x, h2.x, fmaf(ka2.y, h2.y, fmaf(ka2.z, h2.z, fmaf(ka2.w, h2.w, da))));
            da = fmaf(ka3.x, h3.x, fmaf(ka3.y, h3.y, fmaf(ka3.z, h3.z, fmaf(ka3.w, h3.w, da))));
            db = fmaf(kb0.x, h0.x, fmaf(kb0.y, h0.y, fmaf(kb0.z, h0.z, fmaf(kb0.w, h0.w, db))));
            db = fmaf(kb1.x, h1.x, fmaf(kb1.y, h1.y, fmaf(kb1.z, h1.z, fmaf(kb1.w, h1.w, db))));
            db = fmaf(kb2.x, h2.x, fmaf(kb2.y, h2.y, fmaf(kb2.z, h2.z, fmaf(kb2.w, h2.w, db))));
            db = fmaf(kb3.x, h3.x, fmaf(kb3.y, h3.y, fmaf(kb3.z, h3.z, fmaf(kb3.w, h3.w, db))));

            int oka = (ka0.x != PADV) | (ka0.y != PADV) | (ka0.z != PADV) | (ka0.w != PADV)
                    | (ka1.x != PADV) | (ka1.y != PADV) | (ka1.z != PADV) | (ka1.w != PADV)
                    | (ka2.x != PADV) | (ka2.y != PADV) | (ka2.z != PADV) | (ka2.w != PADV)
                    | (ka3.x != PADV) | (ka3.y != PADV) | (ka3.z != PADV) | (ka3.w != PADV);
            int okb = (kb0.x != PADV) | (kb0.y != PADV) | (kb0.z != PADV) | (kb0.w != PADV)
                    | (kb1.x != PADV) | (kb1.y != PADV) | (kb1.z != PADV) | (kb1.w != PADV)
                    | (kb2.x != PADV) | (kb2.y != PADV) | (kb2.z != PADV) | (kb2.w != PADV)
                    | (kb3.x != PADV) | (kb3.y != PADV) | (kb3.z != PADV) | (kb3.w != PADV);

            da = warp_allsum(da);
            db = warp_allsum(db);
            oka = __any_sync(0xffffffffu, oka);
            okb = __any_sync(0xffffffffu, okb);
            float ea = oka ? __expf(da * scale) : 0.0f;
            float eb = (bok && okb) ? __expf(db * scale) : 0.0f;
            if (lane == 0) {
                s_exp[ta - t0] = ea;
                if (bok) s_exp[tb - t0] = eb;
                esum += ea + eb;
            }
            acc0.x = fmaf(ea, va0.x, fmaf(eb, vb0.x, acc0.x));
            acc0.y = fmaf(ea, va0.y, fmaf(eb, vb0.y, acc0.y));
            acc0.z = fmaf(ea, va0.z, fmaf(eb, vb0.z, acc0.z));
            acc0.w = fmaf(ea, va0.w, fmaf(eb, vb0.w, acc0.w));
            acc1.x = fmaf(ea, va1.x, fmaf(eb, vb1.x, acc1.x));
            acc1.y = fmaf(ea, va1.y, fmaf(eb, vb1.y, acc1.y));
            acc1.z = fmaf(ea, va1.z, fmaf(eb, vb1.z, acc1.z));
            acc1.w = fmaf(ea, va1.w, fmaf(eb, vb1.w, acc1.w));
            acc2.x = fmaf(ea, va2.x, fmaf(eb, vb2.x, acc2.x));
            acc2.y = fmaf(ea, va2.y, fmaf(eb, vb2.y, acc2.y));
            acc2.z = fmaf(ea, va2.z, fmaf(eb, vb2.z, acc2.z));
            acc2.w = fmaf(ea, va2.w, fmaf(eb, vb2.w, acc2.w));
            acc3.x = fmaf(ea, va3.x, fmaf(eb, vb3.x, acc3.x));
            acc3.y = fmaf(ea, va3.y, fmaf(eb, vb3.y, acc3.y));
            acc3.z = fmaf(ea, va3.z, fmaf(eb, vb3.z, acc3.z));
            acc3.w = fmaf(ea, va3.w, fmaf(eb, vb3.w, acc3.w));
        }

        // ---- pinned rows (smem) ----
        for (int t = t0 + wid; t < ts; t += NW) {
            const float* row = s_enc + (size_t)(t - t0) * (2 * HID);
            float4 k0 = *(const float4*)(row + base);
            float4 k1 = *(const float4*)(row + base + 128);
            float4 k2 = *(const float4*)(row + base + 256);
            float4 k3 = *(const float4*)(row + base + 384);
            float4 v0 = *(const float4*)(row + HID + base);
            float4 v1 = *(const float4*)(row + HID + base + 128);
            float4 v2 = *(const float4*)(row + HID + base + 256);
            float4 v3 = *(const float4*)(row + HID + base + 384);
            float d = 0.0f;
            d = fmaf(k0.x, h0.x, fmaf(k0.y, h0.y, fmaf(k0.z, h0.z, fmaf(k0.w, h0.w, d))));
            d = fmaf(k1.x, h1.x, fmaf(k1.y, h1.y, fmaf(k1.z, h1.z, fmaf(k1.w, h1.w, d))));
            d = fmaf(k2.x, h2.x, fmaf(k2.y, h2.y, fmaf(k2.z, h2.z, fmaf(k2.w, h2.w, d))));
            d = fmaf(k3.x, h3.x, fmaf(k3.y, h3.y, fmaf(k3.z, h3.z, fmaf(k3.w, h3.w, d))));
            int ok = (k0.x != PADV) | (k0.y != PADV) | (k0.z != PADV) | (k0.w != PADV)
                   | (k1.x != PADV) | (k1.y != PADV) | (k1.z != PADV) | (k1.w != PADV)
                   | (k2.x != PADV) | (k2.y != PADV) | (k2.z != PADV) | (k2.w != PADV)
                   | (k3.x != PADV) | (k3.y != PADV) | (k3.z != PADV) | (k3.w != PADV);
            d = warp_allsum(d);
            ok = __any_sync(0xffffffffu, ok);
            float e = ok ? __expf(d * scale) : 0.0f;
            if (lane == 0) { s_exp[t - t0] = e; esum += e; }
            acc0.x = fmaf(e, v0.x, acc0.x); acc0.y = fmaf(e, v0.y, acc0.y);
            acc0.z = fmaf(e, v0.z, acc0.z); acc0.w = fmaf(e, v0.w, acc0.w);
            acc1.x = fmaf(e, v1.x, acc1.x); acc1.y = fmaf(e, v1.y, acc1.y);
            acc1.z = fmaf(e, v1.z, acc1.z); acc1.w = fmaf(e, v1.w, acc1.w);
            acc2.x = fmaf(e, v2.x, acc2.x); acc2.y = fmaf(e, v2.y, acc2.y);
            acc2.z = fmaf(e, v2.z, acc2.z); acc2.w = fmaf(e, v2.w, acc2.w);
            acc3.x = fmaf(e, v3.x, acc3.x); acc3.y = fmaf(e, v3.y, acc3.y);
            acc3.z = fmaf(e, v3.z, acc3.z); acc3.w = fmaf(e, v3.w, acc3.w);
        }

        // gh precompute for step k+1 (blocks 0-31, one warp per hidden unit)
        if (blk < 32) {
            const int j = blk * NW + wid;
            const int pn = (k + 1) & 1;
            const float* ur = w_hh + (size_t)j * HID;
            const float* uz = ur + (size_t)HID * HID;
            const float* un = uz + (size_t)HID * HID;
            float a3 = 0, a4 = 0, a5 = 0;
            #pragma unroll
            for (int m = 0; m < 4; ++m) {
                int c = base + m * 128;
                float4 hx = *(const float4*)(s_hh + c);
                float4 u0 = *(const float4*)(ur + c);
                float4 u1 = *(const float4*)(uz + c);
                float4 u2 = *(const float4*)(un + c);
                a3 = fmaf(hx.x, u0.x, fmaf(hx.y, u0.y, fmaf(hx.z, u0.z, fmaf(hx.w, u0.w, a3))));
                a4 = fmaf(hx.x, u1.x, fmaf(hx.y, u1.y, fmaf(hx.z, u1.z, fmaf(hx.w, u1.w, a4))));
                a5 = fmaf(hx.x, u2.x, fmaf(hx.y, u2.y, fmaf(hx.z, u2.z, fmaf(hx.w, u2.w, a5))));
            }
            a3 = warp_allsum(a3); a4 = warp_allsum(a4); a5 = warp_allsum(a5);
            if (lane == 0) {
                g_gh[pn][0][j] = a3 + b_hh[j];
                g_gh[pn][1][j] = a4 + b_hh[j + HID];
                g_gh[pn][2][j] = a5 + b_hh[j + 2 * HID];
            }
        }

        // ---- merge: two-phase staging (8 buffers), no smem atomics ----
        if (lane == 0) s_red[wid] = esum;
        if (wid < 8) {
            *(float4*)&s_warp[wid][base]       = acc0;
            *(float4*)&s_warp[wid][base + 128] = acc1;
            *(float4*)&s_warp[wid][base + 256] = acc2;
            *(float4*)&s_warp[wid][base + 384] = acc3;
        }
        __syncthreads();
        if (wid >= 8) {
            float* bdst = s_warp[wid - 8];
            float4 t;
            t = *(float4*)&bdst[base];
            t.x += acc0.x; t.y += acc0.y; t.z += acc0.z; t.w += acc0.w;
            *(float4*)&bdst[base] = t;
            t = *(float4*)&bdst[base + 128];
            t.x += acc1.x; t.y += acc1.y; t.z += acc1.z; t.w += acc1.w;
            *(float4*)&bdst[base + 128] = t;
            t = *(float4*)&bdst[base + 256];
            t.x += acc2.x; t.y += acc2.y; t.z += acc2.z; t.w += acc2.w;
            *(float4*)&bdst[base + 256] = t;
            t = *(float4*)&bdst[base + 384];
            t.x += acc3.x; t.y += acc3.y; t.z += acc3.z; t.w += acc3.w;
            *(float4*)&bdst[base + 384] = t;
        }
        __syncthreads();

        const int bb = k % NBUF;
        float colsum = 0.0f;
        #pragma unroll
        for (int w = 0; w < 8; ++w) colsum += s_warp[w][tid];
        atomicAdd(&g_sumv[bb][tid], colsum);
        if (tid == 0) {
            float tot = 0.0f;
            #pragma unroll
            for (int w = 0; w < NW; ++w) tot += s_red[w];
            atomicAdd(&g_tot[bb], tot);
        }

        grid_barrier();   // the one barrier per step
    }

    if (blk == 0 && tid == 0) out_len[0] = (float)eos_step;
}

extern "C" void kernel_launch(void* const* d_in, const int* in_sizes, int n_in,
                              void* d_out, int out_size) {
    const float* enc   = (const float*)d_in[0];   // encoding [1,16384,1024]
    const float* embed = (const float*)d_in[2];
    const float* w_ih  = (const float*)d_in[3];
    const float* w_hh  = (const float*)d_in[4];
    const float* b_ih  = (const float*)d_in[5];
    const float* b_hh  = (const float*)d_in[6];
    const float* w_out = (const float*)d_in[7];
    const float* b_out = (const float*)d_in[8];
    (void)in_sizes; (void)n_in; (void)out_size;

    const int smem_dyn = (PCACHE * 1024 + NVOCAB * HID) * sizeof(float);   // 202752 B
    static int nblk = 0;
    if (!nblk) {
        cudaFuncSetAttribute(decoder_kernel,
                             cudaFuncAttributeMaxDynamicSharedMemorySize, smem_dyn);
        int dev = 0;
        cudaGetDevice(&dev);
        int sms = 0;
        cudaDeviceGetAttribute(&sms, cudaDevAttrMultiProcessorCount, dev);
        nblk = (sms >= 64 && sms <= MAXBLK) ? sms : 148;
    }
    decoder_kernel<<<nblk, NTHR, smem_dyn>>>(enc, embed, w_ih, w_hh, b_ih, b_hh,
                                             w_out, b_out, (float*)d_out);
}

// round 6
// speedup vs baseline: 2.2445x; 2.2445x over previous
#include <cuda_runtime.h>
#include <math.h>

#define NTHR   512
#define NW     (NTHR / 32)        // 16 warps
#define HID    512
#define TENC   16384
#define NVOCAB 31
#define MAXLEN 100
#define EOSI   29
#define PADV   30.0f
#define NBUF   3
#define MAXBLK 256
#define PCACHE 34                 // enc rows pinned in smem per block

// ---------------- device scratch ----------------
__device__ __align__(16) float g_sumv[NBUF][HID];     // attention summary accumulators
__device__ float g_tot[NBUF];                         // softmax denominators
__device__ __align__(16) float g_gh[2][3][HID];       // w_hh@h + b_hh (r,z,n), double buffered
__device__ __align__(16) float g_gx[NVOCAB][3 * HID]; // w_ih@embed[v] + b_ih
__device__ float g_lh[NVOCAB];                        // w_out[:,512:]@h + b_out (per step)
__device__ volatile int g_arrive[MAXBLK];
__device__ volatile int g_release;

__device__ __forceinline__ float warp_allsum(float v) {
    #pragma unroll
    for (int o = 16; o; o >>= 1) v += __shfl_xor_sync(0xffffffffu, v, o);
    return v;
}

extern __shared__ float s_dyn[];   // [PCACHE*1024] enc rows | [31*512] w_out summary half

__global__ void __launch_bounds__(NTHR, 1)
decoder_kernel(const float* __restrict__ enc,     // [TENC, 1024] keys|values
               const float* __restrict__ embed,   // [31, 512]
               const float* __restrict__ w_ih,    // [1536, 512]
               const float* __restrict__ w_hh,    // [1536, 512]
               const float* __restrict__ b_ih,    // [1536]
               const float* __restrict__ b_hh,    // [1536]
               const float* __restrict__ w_out,   // [31, 1024]
               const float* __restrict__ b_out,   // [31]
               float* __restrict__ out)
{
    const int tid  = threadIdx.x;
    const int blk  = blockIdx.x;
    const int nblk = gridDim.x;
    const int wid  = tid >> 5;
    const int lane = tid & 31;
    const int base = lane * 4;

    float* s_enc   = s_dyn;                   // PCACHE rows of enc
    float* s_woutS = s_dyn + PCACHE * 1024;   // [31][512] summary-half of w_out

    __shared__ __align__(16) float s_hh[HID];          // h (per-block copy)
    __shared__ __align__(16) float s_sum[HID];         // normalized summary
    __shared__ __align__(16) float s_warp[8][HID];     // merge buffers
    __shared__ float s_exp[128];
    __shared__ float s_lh[NVOCAB];
    __shared__ float s_logit[NVOCAB];
    __shared__ float s_red[NW];
    __shared__ int   s_best;

    float* out_logits = out;                        // [100, 31]
    float* out_len    = out + MAXLEN * NVOCAB;      // [1]
    float* out_attn   = out + MAXLEN * NVOCAB + 1;  // [100, 16384]

    int ep = g_release;   // persistent epoch base

    // two-hop barrier: arrive flags -> block0 gather -> single release word
    auto grid_barrier = [&]() {
        ep++;
        __syncthreads();
        __threadfence();
        if (blk == 0) {
            for (int i = tid; i < nblk; i += NTHR)
                if (i > 0) { while (g_arrive[i] < ep) { } }
            __threadfence();
            __syncthreads();
            if (tid == 0) g_release = ep;
        } else {
            if (tid == 0) {
                g_arrive[blk] = ep;
                while (g_release < ep) { }
                __threadfence();
            }
        }
        __syncthreads();
    };

    // ---------------- per-launch init ----------------
    s_hh[tid] = 0.0f;                     // h0 = 0   (NTHR == HID)
    if (tid == 0) s_best = EOSI;          // y0 = embed[EOS]

    // row partition: blocks 0..31 (gh duty) get `light`, rest `heavy` = light+13
    const int heavy = (TENC + 13 * 32 + nblk - 1) / nblk;
    const int light = heavy - 13;
    int t0 = (blk < 32) ? blk * light : 32 * light + (blk - 32) * heavy;
    int t1 = t0 + ((blk < 32) ? light : heavy);
    if (t0 > TENC) t0 = TENC;
    if (t1 > TENC) t1 = TENC;
    const int ts = t0 + PCACHE;          // stream start (every block has >PCACHE rows)

    // pin first PCACHE rows of our range into smem (once per launch)
    for (int i = tid; i < PCACHE * 1024; i += NTHR)
        s_enc[i] = __ldcg(enc + (size_t)t0 * 1024 + i);
    // w_out summary half -> smem
    for (int i = tid; i < NVOCAB * HID; i += NTHR)
        s_woutS[i] = w_out[(size_t)(i >> 9) * 1024 + (i & 511)];

    if (blk == 0) {
        #pragma unroll
        for (int b = 0; b < NBUF; ++b) g_sumv[b][tid] = 0.0f;
        g_gh[0][0][tid] = b_hh[tid];
        g_gh[0][1][tid] = b_hh[tid + HID];
        g_gh[0][2][tid] = b_hh[tid + 2 * HID];
        if (tid == 0) { g_tot[0] = 0.0f; g_tot[1] = 0.0f; g_tot[2] = 0.0f; }
    }
    // gx table: gx[v][u] = w_ih[u] . embed[v] + b_ih[u]
    {
        const int gw = blk * NW + wid;
        for (int r = gw; r < NVOCAB * 3 * HID; r += nblk * NW) {
            const int v = r / (3 * HID);
            const int u = r - v * (3 * HID);
            const float* wrow = w_ih + (size_t)u * HID;
            const float* erow = embed + (size_t)v * HID;
            float a = 0.0f;
            #pragma unroll
            for (int m = 0; m < 4; ++m) {
                int c = base + m * 128;
                float4 w4 = *(const float4*)(wrow + c);
                float4 e4 = *(const float4*)(erow + c);
                a = fmaf(w4.x, e4.x, fmaf(w4.y, e4.y, fmaf(w4.z, e4.z, fmaf(w4.w, e4.w, a))));
            }
            a = warp_allsum(a);
            if (lane == 0) g_gx[v][u] = a + b_ih[u];
        }
    }
    int eos_step = MAXLEN;

    grid_barrier();

    const float scale = 0.04419417382415922f;   // 1/sqrt(512)

    for (int k = 0; k <= MAXLEN; ++k) {
        // ============ Phase A: epilogue of step k-1 (redundant per block) ============
        if (k > 0) {
            const int p = (k - 1) % NBUF;
            const float inv_total = 1.0f / g_tot[p];

            for (int t = t0 + tid; t < t1; t += NTHR)
                out_attn[(size_t)(k - 1) * TENC + t] = s_exp[t - t0] * inv_total;

            s_sum[tid] = g_sumv[p][tid] * inv_total;
            if (tid < NVOCAB) s_lh[tid] = g_lh[tid];

            if (blk == 0) {                       // zero buffer (k+1)%3
                const int zb = (k + 1) % NBUF;
                g_sumv[zb][tid] = 0.0f;
                if (tid == 0) g_tot[zb] = 0.0f;
            }
            __syncthreads();

            // logits: summary half from smem w_out; h half from g_lh
            for (int v = wid; v < NVOCAB; v += NW) {
                const float* wrow = s_woutS + v * HID;
                float dot = 0.0f;
                #pragma unroll
                for (int m = 0; m < 4; ++m) {
                    int c = base + m * 128;
                    float4 w4 = *(const float4*)(wrow + c);
                    float4 x4 = *(const float4*)(s_sum + c);
                    dot = fmaf(w4.x, x4.x, fmaf(w4.y, x4.y, fmaf(w4.z, x4.z, fmaf(w4.w, x4.w, dot))));
                }
                dot = warp_allsum(dot);
                if (lane == 0) {
                    dot += s_lh[v];
                    s_logit[v] = dot;
                    if (blk == 0) out_logits[(k - 1) * NVOCAB + v] = dot;
                }
            }
            __syncthreads();
            if (tid == 0) {
                int best = 0; float bv = s_logit[0];
                #pragma unroll
                for (int v = 1; v < NVOCAB; ++v)
                    if (s_logit[v] > bv) { bv = s_logit[v]; best = v; }
                s_best = best;
                if (blk == 0 && best == EOSI && eos_step == MAXLEN) eos_step = k - 1;
            }
            __syncthreads();
        }

        if (k == MAXLEN) break;

        // GRU pointwise: h^{(k)} = GRU(gx[best], gh, h^{(k-1)})
        {
            const float* gx = g_gx[s_best];
            const int pg = k & 1;
            float r = 1.0f / (1.0f + __expf(-(gx[tid]           + g_gh[pg][0][tid])));
            float z = 1.0f / (1.0f + __expf(-(gx[tid + HID]     + g_gh[pg][1][tid])));
            float n = tanhf(gx[tid + 2 * HID] + r * g_gh[pg][2][tid]);
            s_hh[tid] = (1.0f - z) * n + z * s_hh[tid];
        }
        __syncthreads();

        // ============ Phase B: attention sweep ============
        float4 h0 = *(const float4*)(s_hh + base);
        float4 h1 = *(const float4*)(s_hh + base + 128);
        float4 h2 = *(const float4*)(s_hh + base + 256);
        float4 h3 = *(const float4*)(s_hh + base + 384);

        // lh for next epilogue: block 32+v computes w_out[v,512:].h + b_out[v]
        if (wid == 0 && blk >= 32 && blk < 32 + NVOCAB) {
            const int v = blk - 32;
            const float* wrow = w_out + (size_t)v * 1024 + HID;
            float dot = 0.0f;
            float4 w4;
            w4 = *(const float4*)(wrow + base);
            dot = fmaf(w4.x, h0.x, fmaf(w4.y, h0.y, fmaf(w4.z, h0.z, fmaf(w4.w, h0.w, dot))));
            w4 = *(const float4*)(wrow + base + 128);
            dot = fmaf(w4.x, h1.x, fmaf(w4.y, h1.y, fmaf(w4.z, h1.z, fmaf(w4.w, h1.w, dot))));
            w4 = *(const float4*)(wrow + base + 256);
            dot = fmaf(w4.x, h2.x, fmaf(w4.y, h2.y, fmaf(w4.z, h2.z, fmaf(w4.w, h2.w, dot))));
            w4 = *(const float4*)(wrow + base + 384);
            dot = fmaf(w4.x, h3.x, fmaf(w4.y, h3.y, fmaf(w4.z, h3.z, fmaf(w4.w, h3.w, dot))));
            dot = warp_allsum(dot);
            if (lane == 0) g_lh[v] = dot + b_out[v];
        }

        float4 acc0 = {0,0,0,0}, acc1 = {0,0,0,0}, acc2 = {0,0,0,0}, acc3 = {0,0,0,0};
        float esum = 0.0f;

        // ---- streamed rows (L2, __ldcg), 2 rows per warp-iter ----
        for (int ta = ts + wid; ta < t1; ta += NW * 2) {
            const int tb   = ta + NW;
            const int bok  = (tb < t1);
            const int trb  = bok ? tb : ta;
            const float* ra = enc + (size_t)ta  * (2 * HID);
            const float* rb = enc + (size_t)trb * (2 * HID);
            float4 ka0 = __ldcg((const float4*)(ra + base));
            float4 ka1 = __ldcg((const float4*)(ra + base + 128));
            float4 ka2 = __ldcg((const float4*)(ra + base + 256));
            float4 ka3 = __ldcg((const float4*)(ra + base + 384));
            float4 va0 = __ldcg((const float4*)(ra + HID + base));
            float4 va1 = __ldcg((const float4*)(ra + HID + base + 128));
            float4 va2 = __ldcg((const float4*)(ra + HID + base + 256));
            float4 va3 = __ldcg((const float4*)(ra + HID + base + 384));
            float4 kb0 = __ldcg((const float4*)(rb + base));
            float4 kb1 = __ldcg((const float4*)(rb + base + 128));
            float4 kb2 = __ldcg((const float4*)(rb + base + 256));
            float4 kb3 = __ldcg((const float4*)(rb + base + 384));
            float4 vb0 = __ldcg((const float4*)(rb + HID + base));
            float4 vb1 = __ldcg((const float4*)(rb + HID + base + 128));
            float4 vb2 = __ldcg((const float4*)(rb + HID + base + 256));
            float4 vb3 = __ldcg((const float4*)(rb + HID + base + 384));

            float da = 0.0f, db = 0.0f;
            da = fmaf(ka0.x, h0.x, fmaf(ka0.y, h0.y, fmaf(ka0.z, h0.z, fmaf(ka0.w, h0.w, da))));
            da = fmaf(ka1.x, h1.x, fmaf(ka1.y, h1.y, fmaf(ka1.z, h1.z, fmaf(ka1.w, h1.w, da))));
            da = fmaf(ka2.x, h2.x, fmaf(ka2.y, h2.y, fmaf(ka2.z, h2.z, fmaf(ka2.w, h2.w, da))));
            da = fmaf(ka3.x, h3.x, fmaf(ka3.y, h3.y, fmaf(ka3.z, h3.z, fmaf(ka3.w, h3.w, da))));
            db = fmaf(kb0.x, h0.x, fmaf(kb0.y, h0.y, fmaf(kb0.z, h0.z, fmaf(kb0.w, h0.w, db))));
            db = fmaf(kb1.x, h1.x, fmaf(kb1.y, h1.y, fmaf(kb1.z, h1.z, fmaf(kb1.w, h1.w, db))));
            db = fmaf(kb2.x, h2.x, fmaf(kb2.y, h2.y, fmaf(kb2.z, h2.z, fmaf(kb2.w, h2.w, db))));
            db = fmaf(kb3.x, h3.x, fmaf(kb3.y, h3.y, fmaf(kb3.z, h3.z, fmaf(kb3.w, h3.w, db))));

            int oka = (ka0.x != PADV) | (ka0.y != PADV) | (ka0.z != PADV) | (ka0.w != PADV)
                    | (ka1.x != PADV) | (ka1.y != PADV) | (ka1.z != PADV) | (ka1.w != PADV)
                    | (ka2.x != PADV) | (ka2.y != PADV) | (ka2.z != PADV) | (ka2.w != PADV)
                    | (ka3.x != PADV) | (ka3.y != PADV) | (ka3.z != PADV) | (ka3.w != PADV);
            int okb = (kb0.x != PADV) | (kb0.y != PADV) | (kb0.z != PADV) | (kb0.w != PADV)
                    | (kb1.x != PADV) | (kb1.y != PADV) | (kb1.z != PADV) | (kb1.w != PADV)
                    | (kb2.x != PADV) | (kb2.y != PADV) | (kb2.z != PADV) | (kb2.w != PADV)
                    | (kb3.x != PADV) | (kb3.y != PADV) | (kb3.z != PADV) | (kb3.w != PADV);

            da = warp_allsum(da);
            db = warp_allsum(db);
            oka = __any_sync(0xffffffffu, oka);
            okb = __any_sync(0xffffffffu, okb);
            float ea = oka ? __expf(da * scale) : 0.0f;
            float eb = (bok && okb) ? __expf(db * scale) : 0.0f;
            if (lane == 0) {
                s_exp[ta - t0] = ea;
                if (bok) s_exp[tb - t0] = eb;
                esum += ea + eb;
            }
            acc0.x = fmaf(ea, va0.x, fmaf(eb, vb0.x, acc0.x));
            acc0.y = fmaf(ea, va0.y, fmaf(eb, vb0.y, acc0.y));
            acc0.z = fmaf(ea, va0.z, fmaf(eb, vb0.z, acc0.z));
            acc0.w = fmaf(ea, va0.w, fmaf(eb, vb0.w, acc0.w));
            acc1.x = fmaf(ea, va1.x, fmaf(eb, vb1.x, acc1.x));
            acc1.y = fmaf(ea, va1.y, fmaf(eb, vb1.y, acc1.y));
            acc1.z = fmaf(ea, va1.z, fmaf(eb, vb1.z, acc1.z));
            acc1.w = fmaf(ea, va1.w, fmaf(eb, vb1.w, acc1.w));
            acc2.x = fmaf(ea, va2.x, fmaf(eb, vb2.x, acc2.x));
            acc2.y = fmaf(ea, va2.y, fmaf(eb, vb2.y, acc2.y));
            acc2.z = fmaf(ea, va2.z, fmaf(eb, vb2.z, acc2.z));
            acc2.w = fmaf(ea, va2.w, fmaf(eb, vb2.w, acc2.w));
            acc3.x = fmaf(ea, va3.x, fmaf(eb, vb3.x, acc3.x));
            acc3.y = fmaf(ea, va3.y, fmaf(eb, vb3.y, acc3.y));
            acc3.z = fmaf(ea, va3.z, fmaf(eb, vb3.z, acc3.z));
            acc3.w = fmaf(ea, va3.w, fmaf(eb, vb3.w, acc3.w));
        }

        // ---- pinned rows (smem) ----
        for (int t = t0 + wid; t < ts; t += NW) {
            const float* row = s_enc + (size_t)(t - t0) * (2 * HID);
            float4 k0 = *(const float4*)(row + base);
            float4 k1 = *(const float4*)(row + base + 128);
            float4 k2 = *(const float4*)(row + base + 256);
            float4 k3 = *(const float4*)(row + base + 384);
            float4 v0 = *(const float4*)(row + HID + base);
            float4 v1 = *(const float4*)(row + HID + base + 128);
            float4 v2 = *(const float4*)(row + HID + base + 256);
            float4 v3 = *(const float4*)(row + HID + base + 384);
            float d = 0.0f;
            d = fmaf(k0.x, h0.x, fmaf(k0.y, h0.y, fmaf(k0.z, h0.z, fmaf(k0.w, h0.w, d))));
            d = fmaf(k1.x, h1.x, fmaf(k1.y, h1.y, fmaf(k1.z, h1.z, fmaf(k1.w, h1.w, d))));
            d = fmaf(k2.x, h2.x, fmaf(k2.y, h2.y, fmaf(k2.z, h2.z, fmaf(k2.w, h2.w, d))));
            d = fmaf(k3.x, h3.x, fmaf(k3.y, h3.y, fmaf(k3.z, h3.z, fmaf(k3.w, h3.w, d))));
            int ok = (k0.x != PADV) | (k0.y != PADV) | (k0.z != PADV) | (k0.w != PADV)
                   | (k1.x != PADV) | (k1.y != PADV) | (k1.z != PADV) | (k1.w != PADV)
                   | (k2.x != PADV) | (k2.y != PADV) | (k2.z != PADV) | (k2.w != PADV)
                   | (k3.x != PADV) | (k3.y != PADV) | (k3.z != PADV) | (k3.w != PADV);
            d = warp_allsum(d);
            ok = __any_sync(0xffffffffu, ok);
            float e = ok ? __expf(d * scale) : 0.0f;
            if (lane == 0) { s_exp[t - t0] = e; esum += e; }
            acc0.x = fmaf(e, v0.x, acc0.x); acc0.y = fmaf(e, v0.y, acc0.y);
            acc0.z = fmaf(e, v0.z, acc0.z); acc0.w = fmaf(e, v0.w, acc0.w);
            acc1.x = fmaf(e, v1.x, acc1.x); acc1.y = fmaf(e, v1.y, acc1.y);
            acc1.z = fmaf(e, v1.z, acc1.z); acc1.w = fmaf(e, v1.w, acc1.w);
            acc2.x = fmaf(e, v2.x, acc2.x); acc2.y = fmaf(e, v2.y, acc2.y);
            acc2.z = fmaf(e, v2.z, acc2.z); acc2.w = fmaf(e, v2.w, acc2.w);
            acc3.x = fmaf(e, v3.x, acc3.x); acc3.y = fmaf(e, v3.y, acc3.y);
            acc3.z = fmaf(e, v3.z, acc3.z); acc3.w = fmaf(e, v3.w, acc3.w);
        }

        // gh precompute for step k+1 (blocks 0-31, one warp per hidden unit)
        if (blk < 32) {
            const int j = blk * NW + wid;
            const int pn = (k + 1) & 1;
            const float* ur = w_hh + (size_t)j * HID;
            const float* uz = ur + (size_t)HID * HID;
            const float* un = uz + (size_t)HID * HID;
            float a3 = 0, a4 = 0, a5 = 0;
            #pragma unroll
            for (int m = 0; m < 4; ++m) {
                int c = base + m * 128;
                float4 hx = *(const float4*)(s_hh + c);
                float4 u0 = *(const float4*)(ur + c);
                float4 u1 = *(const float4*)(uz + c);
                float4 u2 = *(const float4*)(un + c);
                a3 = fmaf(hx.x, u0.x, fmaf(hx.y, u0.y, fmaf(hx.z, u0.z, fmaf(hx.w, u0.w, a3))));
                a4 = fmaf(hx.x, u1.x, fmaf(hx.y, u1.y, fmaf(hx.z, u1.z, fmaf(hx.w, u1.w, a4))));
                a5 = fmaf(hx.x, u2.x, fmaf(hx.y, u2.y, fmaf(hx.z, u2.z, fmaf(hx.w, u2.w, a5))));
            }
            a3 = warp_allsum(a3); a4 = warp_allsum(a4); a5 = warp_allsum(a5);
            if (lane == 0) {
                g_gh[pn][0][j] = a3 + b_hh[j];
                g_gh[pn][1][j] = a4 + b_hh[j + HID];
                g_gh[pn][2][j] = a5 + b_hh[j + 2 * HID];
            }
        }

        // ---- merge: two-phase staging (8 buffers), no smem atomics ----
        if (lane == 0) s_red[wid] = esum;
        if (wid < 8) {
            *(float4*)&s_warp[wid][base]       = acc0;
            *(float4*)&s_warp[wid][base + 128] = acc1;
            *(float4*)&s_warp[wid][base + 256] = acc2;
            *(float4*)&s_warp[wid][base + 384] = acc3;
        }
        __syncthreads();
        if (wid >= 8) {
            float* bdst = s_warp[wid - 8];
            float4 t;
            t = *(float4*)&bdst[base];
            t.x += acc0.x; t.y += acc0.y; t.z += acc0.z; t.w += acc0.w;
            *(float4*)&bdst[base] = t;
            t = *(float4*)&bdst[base + 128];
            t.x += acc1.x; t.y += acc1.y; t.z += acc1.z; t.w += acc1.w;
            *(float4*)&bdst[base + 128] = t;
            t = *(float4*)&bdst[base + 256];
            t.x += acc2.x; t.y += acc2.y; t.z += acc2.z; t.w += acc2.w;
            *(float4*)&bdst[base + 256] = t;
            t = *(float4*)&bdst[base + 384];
            t.x += acc3.x; t.y += acc3.y; t.z += acc3.z; t.w += acc3.w;
            *(float4*)&bdst[base + 384] = t;
        }
        __syncthreads();

        const int bb = k % NBUF;
        float colsum = 0.0f;
        #pragma unroll
        for (int w = 0; w < 8; ++w) colsum += s_warp[w][tid];
        atomicAdd(&g_sumv[bb][tid], colsum);
        if (tid == 0) {
            float tot = 0.0f;
            #pragma unroll
            for (int w = 0; w < NW; ++w) tot += s_red[w];
            atomicAdd(&g_tot[bb], tot);
        }

        grid_barrier();   // the one barrier per step
    }

    if (blk == 0 && tid == 0) out_len[0] = (float)eos_step;
}

extern "C" void kernel_launch(void* const* d_in, const int* in_sizes, int n_in,
                              void* d_out, int out_size) {
    const float* enc   = (const float*)d_in[0];   // encoding [1,16384,1024]
    const float* embed = (const float*)d_in[2];
    const float* w_ih  = (const float*)d_in[3];
    const float* w_hh  = (const float*)d_in[4];
    const float* b_ih  = (const float*)d_in[5];
    const float* b_hh  = (const float*)d_in[6];
    const float* w_out = (const float*)d_in[7];
    const float* b_out = (const float*)d_in[8];
    (void)in_sizes; (void)n_in; (void)out_size;

    const int smem_dyn = (PCACHE * 1024 + NVOCAB * HID) * sizeof(float);   // 202752 B
    static int nblk = 0;
    if (!nblk) {
        cudaFuncSetAttribute(decoder_kernel,
                             cudaFuncAttributeMaxDynamicSharedMemorySize, smem_dyn);
        int dev = 0;
        cudaGetDevice(&dev);
        int sms = 0;
        cudaDeviceGetAttribute(&sms, cudaDevAttrMultiProcessorCount, dev);
        nblk = (sms >= 64 && sms <= MAXBLK) ? sms : 148;
    }
    decoder_kernel<<<nblk, NTHR, smem_dyn>>>(enc, embed, w_ih, w_hh, b_ih, b_hh,
                                             w_out, b_out, (float*)d_out);
}

// round 7
// speedup vs baseline: 2.4158x; 1.0763x over previous
#include <cuda_runtime.h>
#include <math.h>

#define NTHR   512
#define NW     (NTHR / 32)        // 16 warps
#define HID    512
#define TENC   16384
#define NVOCAB 31
#define MAXLEN 100
#define EOSI   29
#define PADV   30.0f
#define NBUF   3
#define MAXBLK 256
#define PCACHE 34                 // enc rows pinned in smem per block
#define LDSTRIDE 32               // g_ldot padding: one 128B line per vocab entry

// ---------------- device scratch ----------------
__device__ float g_ldot[NBUF][NVOCAB * LDSTRIDE];     // partial logit dots (summary part)
__device__ float g_tot[NBUF];                         // softmax denominators
__device__ __align__(16) float g_gh[2][3][HID];       // w_hh@h + b_hh (r,z,n), double buffered
__device__ __align__(16) float g_gx[NVOCAB][3 * HID]; // w_ih@embed[v] + b_ih
__device__ float g_lh[2][NVOCAB];                     // w_out[:,512:]@h + b_out, double buffered
__device__ volatile int g_arrive[MAXBLK];
__device__ volatile int g_release;

__device__ __forceinline__ float warp_allsum(float v) {
    #pragma unroll
    for (int o = 16; o; o >>= 1) v += __shfl_xor_sync(0xffffffffu, v, o);
    return v;
}
__device__ __forceinline__ int ld_acq(volatile int* p) {
    int v;
    asm volatile("ld.acquire.gpu.s32 %0, [%1];" : "=r"(v) : "l"((int*)p) : "memory");
    return v;
}
__device__ __forceinline__ void st_rel(volatile int* p, int v) {
    asm volatile("st.release.gpu.s32 [%0], %1;" :: "l"((int*)p), "r"(v) : "memory");
}

extern __shared__ float s_dyn[];   // [PCACHE*1024] enc rows | [31*512] w_out summary half

__global__ void __launch_bounds__(NTHR, 1)
decoder_kernel(const float* __restrict__ enc,     // [TENC, 1024] keys|values
               const float* __restrict__ embed,   // [31, 512]
               const float* __restrict__ w_ih,    // [1536, 512]
               const float* __restrict__ w_hh,    // [1536, 512]
               const float* __restrict__ b_ih,    // [1536]
               const float* __restrict__ b_hh,    // [1536]
               const float* __restrict__ w_out,   // [31, 1024]
               const float* __restrict__ b_out,   // [31]
               float* __restrict__ out)
{
    const int tid  = threadIdx.x;
    const int blk  = blockIdx.x;
    const int nblk = gridDim.x;
    const int wid  = tid >> 5;
    const int lane = tid & 31;
    const int base = lane * 4;

    float* s_enc   = s_dyn;                   // PCACHE rows of enc
    float* s_woutS = s_dyn + PCACHE * 1024;   // [31][512] summary-half of w_out

    __shared__ __align__(16) float s_hh[HID];          // h (per-block copy)
    __shared__ __align__(16) float s_sum[HID];         // block partial summary
    __shared__ __align__(16) float s_warp[8][HID];     // merge buffers
    __shared__ float s_exp[128];
    __shared__ float s_logit[NVOCAB];
    __shared__ float s_red[NW];
    __shared__ int   s_best;

    float* out_logits = out;                        // [100, 31]
    float* out_len    = out + MAXLEN * NVOCAB;      // [1]
    float* out_attn   = out + MAXLEN * NVOCAB + 1;  // [100, 16384]

    int ep = g_release;   // persistent epoch base

    // two-hop barrier: arrive flags -> block0 gather -> single release word
    auto grid_barrier = [&]() {
        ep++;
        __syncthreads();
        if (blk == 0) {
            if (tid == 0) st_rel(&g_arrive[0], ep);
            for (int i = tid; i < nblk; i += NTHR)
                if (i > 0) { while (ld_acq(&g_arrive[i]) < ep) { } }
            __syncthreads();
            if (tid == 0) st_rel(&g_release, ep);
        } else {
            if (tid == 0) {
                st_rel(&g_arrive[blk], ep);
                while (ld_acq(&g_release) < ep) { }
            }
        }
        __syncthreads();
    };

    // ---------------- per-launch init ----------------
    s_hh[tid] = 0.0f;                     // h0 = 0   (NTHR == HID)
    if (tid == 0) s_best = EOSI;          // y0 = embed[EOS]

    // uniform row partition: blocks 0..119 get 108 rows, 120..151 get 107 (for nblk=152)
    const int rq = TENC / nblk;
    const int rx = TENC - rq * nblk;       // first rx blocks get rq+1
    int t0 = blk * rq + (blk < rx ? blk : rx);
    int t1 = t0 + rq + (blk < rx ? 1 : 0);
    const int ts = t0 + PCACHE;           // stream start (rows per block > PCACHE)

    // pin first PCACHE rows of our range into smem (once per launch)
    for (int i = tid; i < PCACHE * 1024; i += NTHR)
        s_enc[i] = __ldcg(enc + (size_t)t0 * 1024 + i);
    // w_out summary half -> smem
    for (int i = tid; i < NVOCAB * HID; i += NTHR)
        s_woutS[i] = w_out[(size_t)(i >> 9) * 1024 + (i & 511)];

    if (blk == 0) {
        g_gh[0][0][tid] = b_hh[tid];
        g_gh[0][1][tid] = b_hh[tid + HID];
        g_gh[0][2][tid] = b_hh[tid + 2 * HID];
        if (wid == 1 && lane < NVOCAB) {
            #pragma unroll
            for (int b = 0; b < NBUF; ++b) g_ldot[b][lane * LDSTRIDE] = 0.0f;
        }
        if (tid == 0) { g_tot[0] = 0.0f; g_tot[1] = 0.0f; g_tot[2] = 0.0f; }
    }
    // gx table: gx[v][u] = w_ih[u] . embed[v] + b_ih[u]
    {
        const int gw = blk * NW + wid;
        for (int r = gw; r < NVOCAB * 3 * HID; r += nblk * NW) {
            const int v = r / (3 * HID);
            const int u = r - v * (3 * HID);
            const float* wrow = w_ih + (size_t)u * HID;
            const float* erow = embed + (size_t)v * HID;
            float a = 0.0f;
            #pragma unroll
            for (int m = 0; m < 4; ++m) {
                int c = base + m * 128;
                float4 w4 = *(const float4*)(wrow + c);
                float4 e4 = *(const float4*)(erow + c);
                a = fmaf(w4.x, e4.x, fmaf(w4.y, e4.y, fmaf(w4.z, e4.z, fmaf(w4.w, e4.w, a))));
            }
            a = warp_allsum(a);
            if (lane == 0) g_gx[v][u] = a + b_ih[u];
        }
    }
    int eos_step = MAXLEN;

    grid_barrier();

    const float scale = 0.04419417382415922f;   // 1/sqrt(512)

    for (int k = 0; k <= MAXLEN; ++k) {
        // ============ Phase A: tiny epilogue of step k-1 (redundant per block) ============
        if (k > 0) {
            const int p  = (k - 1) % NBUF;
            const int pl = (k - 1) & 1;
            const float inv_total = 1.0f / g_tot[p];

            // prefetch gh for the GRU (independent of argmax)
            const int pg = k & 1;
            const float gh0 = g_gh[pg][0][tid];
            const float gh1 = g_gh[pg][1][tid];
            const float gh2 = g_gh[pg][2][tid];

            if (wid == 0) {
                float lg = -1e30f;
                if (lane < NVOCAB)
                    lg = g_ldot[p][lane * LDSTRIDE] * inv_total + g_lh[pl][lane];
                // shfl argmax, first-index tie-break
                unsigned kb = __float_as_uint(lg);
                kb = (kb & 0x80000000u) ? ~kb : (kb | 0x80000000u);
                unsigned long long pk = ((unsigned long long)kb << 6) | (unsigned)(63 - lane);
                #pragma unroll
                for (int o = 16; o; o >>= 1) {
                    unsigned long long q = __shfl_xor_sync(0xffffffffu, pk, o);
                    if (q > pk) pk = q;
                }
                if (lane == 0) {
                    int best = 63 - (int)(pk & 63u);
                    s_best = best;
                    if (blk == 0 && best == EOSI && eos_step == MAXLEN) eos_step = k - 1;
                }
                if (blk == 0 && lane < NVOCAB)
                    out_logits[(k - 1) * NVOCAB + lane] = lg;
            }
            // zero buffer (k+1)%3 (block 0, warp 1)
            if (blk == 0 && wid == 1) {
                const int zb = (k + 1) % NBUF;
                if (lane < NVOCAB) g_ldot[zb][lane * LDSTRIDE] = 0.0f;
                if (lane == 31) g_tot[zb] = 0.0f;
            }
            // attention output for step k-1
            for (int t = t0 + tid; t < t1; t += NTHR)
                out_attn[(size_t)(k - 1) * TENC + t] = s_exp[t - t0] * inv_total;
            __syncthreads();

            if (k == MAXLEN) break;

            // GRU pointwise: h^{(k)} = GRU(gx[best], gh, h^{(k-1)})
            const float* gx = g_gx[s_best];
            float r = 1.0f / (1.0f + __expf(-(gx[tid]           + gh0)));
            float z = 1.0f / (1.0f + __expf(-(gx[tid + HID]     + gh1)));
            float n = tanhf(gx[tid + 2 * HID] + r * gh2);
            s_hh[tid] = (1.0f - z) * n + z * s_hh[tid];
            __syncthreads();
        } else {
            // k == 0: h^{(0)} = GRU(gx[EOS], b_hh, 0)
            const float* gx = g_gx[EOSI];
            float r = 1.0f / (1.0f + __expf(-(gx[tid]           + g_gh[0][0][tid])));
            float z = 1.0f / (1.0f + __expf(-(gx[tid + HID]     + g_gh[0][1][tid])));
            float n = tanhf(gx[tid + 2 * HID] + r * g_gh[0][2][tid]);
            s_hh[tid] = (1.0f - z) * n;
            __syncthreads();
        }

        // ============ Phase B: attention sweep ============
        float4 h0 = *(const float4*)(s_hh + base);
        float4 h1 = *(const float4*)(s_hh + base + 128);
        float4 h2 = *(const float4*)(s_hh + base + 256);
        float4 h3 = *(const float4*)(s_hh + base + 384);

        // lh duty: blocks 1..31, warp 0: g_lh[k&1][v] = w_out[v,512:].h + b_out[v]
        if (wid == 0 && blk >= 1 && blk <= NVOCAB) {
            const int v = blk - 1;
            const float* wrow = w_out + (size_t)v * 1024 + HID;
            float dot = 0.0f;
            float4 w4;
            w4 = *(const float4*)(wrow + base);
            dot = fmaf(w4.x, h0.x, fmaf(w4.y, h0.y, fmaf(w4.z, h0.z, fmaf(w4.w, h0.w, dot))));
            w4 = *(const float4*)(wrow + base + 128);
            dot = fmaf(w4.x, h1.x, fmaf(w4.y, h1.y, fmaf(w4.z, h1.z, fmaf(w4.w, h1.w, dot))));
            w4 = *(const float4*)(wrow + base + 256);
            dot = fmaf(w4.x, h2.x, fmaf(w4.y, h2.y, fmaf(w4.z, h2.z, fmaf(w4.w, h2.w, dot))));
            w4 = *(const float4*)(wrow + base + 384);
            dot = fmaf(w4.x, h3.x, fmaf(w4.y, h3.y, fmaf(w4.z, h3.z, fmaf(w4.w, h3.w, dot))));
            dot = warp_allsum(dot);
            if (lane == 0) g_lh[k & 1][v] = dot + b_out[v];
        }

        float4 acc0 = {0,0,0,0}, acc1 = {0,0,0,0}, acc2 = {0,0,0,0}, acc3 = {0,0,0,0};
        float esum = 0.0f;

        // ---- streamed rows (L2, __ldcg), 2 rows per warp-iter ----
        for (int ta = ts + wid; ta < t1; ta += NW * 2) {
            const int tb   = ta + NW;
            const int bok  = (tb < t1);
            const int trb  = bok ? tb : ta;
            const float* ra = enc + (size_t)ta  * (2 * HID);
            const float* rb = enc + (size_t)trb * (2 * HID);
            float4 ka0 = __ldcg((const float4*)(ra + base));
            float4 ka1 = __ldcg((const float4*)(ra + base + 128));
            float4 ka2 = __ldcg((const float4*)(ra + base + 256));
            float4 ka3 = __ldcg((const float4*)(ra + base + 384));
            float4 va0 = __ldcg((const float4*)(ra + HID + base));
            float4 va1 = __ldcg((const float4*)(ra + HID + base + 128));
            float4 va2 = __ldcg((const float4*)(ra + HID + base + 256));
            float4 va3 = __ldcg((const float4*)(ra + HID + base + 384));
            float4 kb0 = __ldcg((const float4*)(rb + base));
            float4 kb1 = __ldcg((const float4*)(rb + base + 128));
            float4 kb2 = __ldcg((const float4*)(rb + base + 256));
            float4 kb3 = __ldcg((const float4*)(rb + base + 384));
            float4 vb0 = __ldcg((const float4*)(rb + HID + base));
            float4 vb1 = __ldcg((const float4*)(rb + HID + base + 128));
            float4 vb2 = __ldcg((const float4*)(rb + HID + base + 256));
            float4 vb3 = __ldcg((const float4*)(rb + HID + base + 384));

            float da = 0.0f, db = 0.0f;
            da = fmaf(ka0.x, h0.x, fmaf(ka0.y, h0.y, fmaf(ka0.z, h0.z, fmaf(ka0.w, h0.w, da))));
            da = fmaf(ka1.x, h1.x, fmaf(ka1.y, h1.y, fmaf(ka1.z, h1.z, fmaf(ka1.w, h1.w, da))));
            da = fmaf(ka2.x, h2.x, fmaf(ka2.y, h2.y, fmaf(ka2.z, h2.z, fmaf(ka2.w, h2.w, da))));
            da = fmaf(ka3.x, h3.x, fmaf(ka3.y, h3.y, fmaf(ka3.z, h3.z, fmaf(ka3.w, h3.w, da))));
            db = fmaf(kb0.x, h0.x, fmaf(kb0.y, h0.y, fmaf(kb0.z, h0.z, fmaf(kb0.w, h0.w, db))));
            db = fmaf(kb1.x, h1.x, fmaf(kb1.y, h1.y, fmaf(kb1.z, h1.z, fmaf(kb1.w, h1.w, db))));
            db = fmaf(kb2.x, h2.x, fmaf(kb2.y, h2.y, fmaf(kb2.z, h2.z, fmaf(kb2.w, h2.w, db))));
            db = fmaf(kb3.x, h3.x, fmaf(kb3.y, h3.y, fmaf(kb3.z, h3.z, fmaf(kb3.w, h3.w, db))));

            int oka = (ka0.x != PADV) | (ka0.y != PADV) | (ka0.z != PADV) | (ka0.w != PADV)
                    | (ka1.x != PADV) | (ka1.y != PADV) | (ka1.z != PADV) | (ka1.w != PADV)
                    | (ka2.x != PADV) | (ka2.y != PADV) | (ka2.z != PADV) | (ka2.w != PADV)
                    | (ka3.x != PADV) | (ka3.y != PADV) | (ka3.z != PADV) | (ka3.w != PADV);
            int okb = (kb0.x != PADV) | (kb0.y != PADV) | (kb0.z != PADV) | (kb0.w != PADV)
                    | (kb1.x != PADV) | (kb1.y != PADV) | (kb1.z != PADV) | (kb1.w != PADV)
                    | (kb2.x != PADV) | (kb2.y != PADV) | (kb2.z != PADV) | (kb2.w != PADV)
                    | (kb3.x != PADV) | (kb3.y != PADV) | (kb3.z != PADV) | (kb3.w != PADV);

            da = warp_allsum(da);
            db = warp_allsum(db);
            oka = __any_sync(0xffffffffu, oka);
            okb = __any_sync(0xffffffffu, okb);
            float ea = oka ? __expf(da * scale) : 0.0f;
            float eb = (bok && okb) ? __expf(db * scale) : 0.0f;
            if (lane == 0) {
                s_exp[ta - t0] = ea;
                if (bok) s_exp[tb - t0] = eb;
                esum += ea + eb;
            }
            acc0.x = fmaf(ea, va0.x, fmaf(eb, vb0.x, acc0.x));
            acc0.y = fmaf(ea, va0.y, fmaf(eb, vb0.y, acc0.y));
            acc0.z = fmaf(ea, va0.z, fmaf(eb, vb0.z, acc0.z));
            acc0.w = fmaf(ea, va0.w, fmaf(eb, vb0.w, acc0.w));
            acc1.x = fmaf(ea, va1.x, fmaf(eb, vb1.x, acc1.x));
            acc1.y = fmaf(ea, va1.y, fmaf(eb, vb1.y, acc1.y));
            acc1.z = fmaf(ea, va1.z, fmaf(eb, vb1.z, acc1.z));
            acc1.w = fmaf(ea, va1.w, fmaf(eb, vb1.w, acc1.w));
            acc2.x = fmaf(ea, va2.x, fmaf(eb, vb2.x, acc2.x));
            acc2.y = fmaf(ea, va2.y, fmaf(eb, vb2.y, acc2.y));
            acc2.z = fmaf(ea, va2.z, fmaf(eb, vb2.z, acc2.z));
            acc2.w = fmaf(ea, va2.w, fmaf(eb, vb2.w, acc2.w));
            acc3.x = fmaf(ea, va3.x, fmaf(eb, vb3.x, acc3.x));
            acc3.y = fmaf(ea, va3.y, fmaf(eb, vb3.y, acc3.y));
            acc3.z = fmaf(ea, va3.z, fmaf(eb, vb3.z, acc3.z));
            acc3.w = fmaf(ea, va3.w, fmaf(eb, vb3.w, acc3.w));
        }

        // ---- pinned rows (smem) ----
        for (int t = t0 + wid; t < ts; t += NW) {
            const float* row = s_enc + (size_t)(t - t0) * (2 * HID);
            float4 k0 = *(const float4*)(row + base);
            float4 k1 = *(const float4*)(row + base + 128);
            float4 k2 = *(const float4*)(row + base + 256);
            float4 k3 = *(const float4*)(row + base + 384);
            float4 v0 = *(const float4*)(row + HID + base);
            float4 v1 = *(const float4*)(row + HID + base + 128);
            float4 v2 = *(const float4*)(row + HID + base + 256);
            float4 v3 = *(const float4*)(row + HID + base + 384);
            float d = 0.0f;
            d = fmaf(k0.x, h0.x, fmaf(k0.y, h0.y, fmaf(k0.z, h0.z, fmaf(k0.w, h0.w, d))));
            d = fmaf(k1.x, h1.x, fmaf(k1.y, h1.y, fmaf(k1.z, h1.z, fmaf(k1.w, h1.w, d))));
            d = fmaf(k2.x, h2.x, fmaf(k2.y, h2.y, fmaf(k2.z, h2.z, fmaf(k2.w, h2.w, d))));
            d = fmaf(k3.x, h3.x, fmaf(k3.y, h3.y, fmaf(k3.z, h3.z, fmaf(k3.w, h3.w, d))));
            int ok = (k0.x != PADV) | (k0.y != PADV) | (k0.z != PADV) | (k0.w != PADV)
                   | (k1.x != PADV) | (k1.y != PADV) | (k1.z != PADV) | (k1.w != PADV)
                   | (k2.x != PADV) | (k2.y != PADV) | (k2.z != PADV) | (k2.w != PADV)
                   | (k3.x != PADV) | (k3.y != PADV) | (k3.z != PADV) | (k3.w != PADV);
            d = warp_allsum(d);
            ok = __any_sync(0xffffffffu, ok);
            float e = ok ? __expf(d * scale) : 0.0f;
            if (lane == 0) { s_exp[t - t0] = e; esum += e; }
            acc0.x = fmaf(e, v0.x, acc0.x); acc0.y = fmaf(e, v0.y, acc0.y);
            acc0.z = fmaf(e, v0.z, acc0.z); acc0.w = fmaf(e, v0.w, acc0.w);
            acc1.x = fmaf(e, v1.x, acc1.x); acc1.y = fmaf(e, v1.y, acc1.y);
            acc1.z = fmaf(e, v1.z, acc1.z); acc1.w = fmaf(e, v1.w, acc1.w);
            acc2.x = fmaf(e, v2.x, acc2.x); acc2.y = fmaf(e, v2.y, acc2.y);
            acc2.z = fmaf(e, v2.z, acc2.z); acc2.w = fmaf(e, v2.w, acc2.w);
            acc3.x = fmaf(e, v3.x, acc3.x); acc3.y = fmaf(e, v3.y, acc3.y);
            acc3.z = fmaf(e, v3.z, acc3.z); acc3.w = fmaf(e, v3.w, acc3.w);
        }

        // gh duty: blocks 32..127, one dot per warp (1536 total)
        if (blk >= 32 && blk < 128) {
            const int d  = (blk - 32) * NW + wid;   // 0..1535
            const int g  = d >> 9;
            const int j  = d & 511;
            const int pn = (k + 1) & 1;
            const float* ur = w_hh + (size_t)(g * HID + j) * HID;
            float a = 0.0f;
            #pragma unroll
            for (int m = 0; m < 4; ++m) {
                int c = base + m * 128;
                float4 hx = *(const float4*)(s_hh + c);
                float4 u4 = *(const float4*)(ur + c);
                a = fmaf(hx.x, u4.x, fmaf(hx.y, u4.y, fmaf(hx.z, u4.z, fmaf(hx.w, u4.w, a))));
            }
            a = warp_allsum(a);
            if (lane == 0) g_gh[pn][g][j] = a + b_hh[g * HID + j];
        }

        // ---- merge: two-phase staging -> block partial summary in s_sum ----
        if (lane == 0) s_red[wid] = esum;
        if (wid < 8) {
            *(float4*)&s_warp[wid][base]       = acc0;
            *(float4*)&s_warp[wid][base + 128] = acc1;
            *(float4*)&s_warp[wid][base + 256] = acc2;
            *(float4*)&s_warp[wid][base + 384] = acc3;
        }
        __syncthreads();
        if (wid >= 8) {
            float* bdst = s_warp[wid - 8];
            float4 t;
            t = *(float4*)&bdst[base];
            t.x += acc0.x; t.y += acc0.y; t.z += acc0.z; t.w += acc0.w;
            *(float4*)&bdst[base] = t;
            t = *(float4*)&bdst[base + 128];
            t.x += acc1.x; t.y += acc1.y; t.z += acc1.z; t.w += acc1.w;
            *(float4*)&bdst[base + 128] = t;
            t = *(float4*)&bdst[base + 256];
            t.x += acc2.x; t.y += acc2.y; t.z += acc2.z; t.w += acc2.w;
            *(float4*)&bdst[base + 256] = t;
            t = *(float4*)&bdst[base + 384];
            t.x += acc3.x; t.y += acc3.y; t.z += acc3.z; t.w += acc3.w;
            *(float4*)&bdst[base + 384] = t;
        }
        __syncthreads();
        {
            float colsum = 0.0f;
            #pragma unroll
            for (int w = 0; w < 8; ++w) colsum += s_warp[w][tid];
            s_sum[tid] = colsum;
        }
        __syncthreads();

        // ---- partial logit dots: ldot[v] += w_outS[v] . s_sum  (31 atomics/block) ----
        const int bb = k % NBUF;
        for (int v = wid; v < NVOCAB; v += NW) {
            const float* wrow = s_woutS + v * HID;
            float dot = 0.0f;
            #pragma unroll
            for (int m = 0; m < 4; ++m) {
                int c = base + m * 128;
                float4 w4 = *(const float4*)(wrow + c);
                float4 x4 = *(const float4*)(s_sum + c);
                dot = fmaf(w4.x, x4.x, fmaf(w4.y, x4.y, fmaf(w4.z, x4.z, fmaf(w4.w, x4.w, dot))));
            }
            dot = warp_allsum(dot);
            if (lane == 0) atomicAdd(&g_ldot[bb][v * LDSTRIDE], dot);
        }
        if (tid == 0) {
            float tot = 0.0f;
            #pragma unroll
            for (int w = 0; w < NW; ++w) tot += s_red[w];
            atomicAdd(&g_tot[bb], tot);
        }

        grid_barrier();   // the one barrier per step
    }

    if (blk == 0 && tid == 0) out_len[0] = (float)eos_step;
}

extern "C" void kernel_launch(void* const* d_in, const int* in_sizes, int n_in,
                              void* d_out, int out_size) {
    const float* enc   = (const float*)d_in[0];   // encoding [1,16384,1024]
    const float* embed = (const float*)d_in[2];
    const float* w_ih  = (const float*)d_in[3];
    const float* w_hh  = (const float*)d_in[4];
    const float* b_ih  = (const float*)d_in[5];
    const float* b_hh  = (const float*)d_in[6];
    const float* w_out = (const float*)d_in[7];
    const float* b_out = (const float*)d_in[8];
    (void)in_sizes; (void)n_in; (void)out_size;

    const int smem_dyn = (PCACHE * 1024 + NVOCAB * HID) * sizeof(float);   // 202752 B
    static int nblk = 0;
    if (!nblk) {
        cudaFuncSetAttribute(decoder_kernel,
                             cudaFuncAttributeMaxDynamicSharedMemorySize, smem_dyn);
        int dev = 0;
        cudaGetDevice(&dev);
        int sms = 0;
        cudaDeviceGetAttribute(&sms, cudaDevAttrMultiProcessorCount, dev);
        nblk = (sms >= 64 && sms <= MAXBLK) ? sms : 148;
    }
    decoder_kernel<<<nblk, NTHR, smem_dyn>>>(enc, embed, w_ih, w_hh, b_ih, b_hh,
                                             w_out, b_out, (float*)d_out);
}